// round 10
// baseline (speedup 1.0000x reference)
#include <cuda_runtime.h>
#include <cmath>

#define B 8
#define S 1024
#define D 768
#define H 4
#define DV 192
#define AD 32

// ------------------------- scratch (device globals, no allocs) -------------
__device__ float g_q[B*S*AD];
__device__ float g_k[B*S*AD];
__device__ float g_att[B*S*D];
__device__ float g_pos[B*S*D];
__device__ float g_pam[B*S*D];

// ------------------------- q/k projection: relu(x@W + b), D->32 ------------
__global__ void qk_proj_kernel(const float* __restrict__ x,
                               const float* __restrict__ Wq, const float* __restrict__ bq,
                               const float* __restrict__ Wk, const float* __restrict__ bk,
                               float* __restrict__ qo, float* __restrict__ ko)
{
    __shared__ float xs[4*D];
    int row0 = blockIdx.x * 4;
    int tid = threadIdx.x;
    const float4* xg = (const float4*)(x + (size_t)row0 * D);
    for (int i = tid; i < 4*D/4; i += 256)
        ((float4*)xs)[i] = xg[i];
    __syncthreads();
    int g = tid >> 6;          // 4 rows per block
    int c = tid & 63;          // 0..31 -> q cols, 32..63 -> k cols
    const float* xr = xs + g * D;
    const float* W = (c < AD) ? Wq : Wk;
    int col = c & (AD-1);
    float s = 0.f;
    #pragma unroll 8
    for (int d = 0; d < D; d++)
        s = fmaf(xr[d], W[d*AD + col], s);
    s += (c < AD) ? bq[col] : bk[col];
    s = fmaxf(s, 0.f);
    int row = row0 + g;
    float* o = (c < AD) ? qo : ko;
    o[(size_t)row*AD + col] = s;
}

// ------------------------- fused flash attention ---------------------------
// out[b, i, h*DV + d] = sum_j softmax_j( Q[i]·K[j] * scale, masked ) * V[j, d]
// mask(i,j) invalid -> score = -1e7f (finite, matches reference semantics:
// an all-masked row degenerates to a uniform average, NOT zeros).
template<int DQK>
__global__ void attn_kernel(const float* __restrict__ Qm,
                            const float* __restrict__ Km,
                            int qk_stride,
                            const float* __restrict__ Vm,   // x [B,S,D]
                            const int* __restrict__ mask,   // [B,S]
                            float* __restrict__ Om,         // [B,S,D]
                            float scale)
{
    constexpr int TK = 32;           // keys per tile
    constexpr int RW = 4;            // rows per warp
    constexpr int NW = 8;            // warps per block
    constexpr int RB = RW*NW;        // 32 rows per block
    constexpr int KSs = DQK + 4;     // padded row stride (== 4 mod 32: float4-phase friendly)
    constexpr int UV = DV/32;        // 6 v-columns per lane

    extern __shared__ float smem[];
    float* Qs = smem;                    // RB*KSs
    float* Ks = Qs + RB*KSs;             // TK*KSs
    float* Vs = Ks + TK*KSs;             // TK*DV
    int*   kms = (int*)(Vs + TK*DV);     // TK

    int b = blockIdx.z, h = blockIdx.y;
    int row0 = blockIdx.x * RB;
    int tid = threadIdx.x;
    int lane = tid & 31;
    int w = tid >> 5;

    const float* Qbase = Qm + (size_t)b*S*qk_stride + h*DQK;
    const float* Kbase = Km + (size_t)b*S*qk_stride + h*DQK;
    const float* Vbase = Vm + (size_t)b*S*D + h*DV;
    const int* mb = mask + b*S;

    // load the 32 query rows once
    for (int i = tid; i < RB*DQK; i += NW*32) {
        int r = i / DQK, d = i % DQK;
        Qs[r*KSs + d] = Qbase[(size_t)(row0 + r)*qk_stride + d];
    }

    int rmask[RW];
    #pragma unroll
    for (int r = 0; r < RW; r++) rmask[r] = mb[row0 + w*RW + r];

    float m_[RW], l_[RW], acc[RW][UV];
    #pragma unroll
    for (int r = 0; r < RW; r++) {
        m_[r] = -INFINITY; l_[r] = 0.f;
        #pragma unroll
        for (int u = 0; u < UV; u++) acc[r][u] = 0.f;
    }

    for (int t = 0; t < S/TK; t++) {
        int k0 = t * TK;
        __syncthreads();
        // K tile
        for (int i = tid; i < TK*(DQK/4); i += NW*32) {
            int j = i / (DQK/4), d4 = i % (DQK/4);
            float4 v = *(const float4*)&Kbase[(size_t)(k0+j)*qk_stride + d4*4];
            float* kd = &Ks[j*KSs + d4*4];
            kd[0]=v.x; kd[1]=v.y; kd[2]=v.z; kd[3]=v.w;
        }
        // V tile
        for (int i = tid; i < TK*(DV/4); i += NW*32) {
            int j = i / (DV/4), d4 = i % (DV/4);
            *(float4*)&Vs[j*DV + d4*4] =
                *(const float4*)&Vbase[(size_t)(k0+j)*D + d4*4];
        }
        if (tid < TK) kms[tid] = mb[k0 + tid];
        __syncthreads();

        int km = kms[lane];
        const float* krow = &Ks[lane*KSs];
        float s4[RW];
        #pragma unroll
        for (int r = 0; r < RW; r++) s4[r] = 0.f;
        #pragma unroll 8
        for (int d4 = 0; d4 < DQK/4; d4++) {
            float4 kb = *(const float4*)&krow[d4*4];
            #pragma unroll
            for (int r = 0; r < RW; r++) {
                float4 qa = *(const float4*)&Qs[(w*RW+r)*KSs + d4*4];
                s4[r] = fmaf(qa.x, kb.x, s4[r]);
                s4[r] = fmaf(qa.y, kb.y, s4[r]);
                s4[r] = fmaf(qa.z, kb.z, s4[r]);
                s4[r] = fmaf(qa.w, kb.w, s4[r]);
            }
        }

        float pv[RW];
        #pragma unroll
        for (int r = 0; r < RW; r++) {
            float s = s4[r] * scale;
            s = (rmask[r] && km) ? s : -1e7f;
            float tmax = s;
            #pragma unroll
            for (int o = 16; o; o >>= 1)
                tmax = fmaxf(tmax, __shfl_xor_sync(0xffffffffu, tmax, o));
            float mnew = fmaxf(m_[r], tmax);
            float p = __expf(s - mnew);
            float psum = p;
            #pragma unroll
            for (int o = 16; o; o >>= 1)
                psum += __shfl_xor_sync(0xffffffffu, psum, o);
            if (mnew > m_[r]) {                        // warp-uniform branch
                float alpha = __expf(m_[r] - mnew);    // exp(-inf)=0 handles init
                l_[r] = fmaf(l_[r], alpha, psum);
                #pragma unroll
                for (int u = 0; u < UV; u++) acc[r][u] *= alpha;
                m_[r] = mnew;
            } else {
                l_[r] += psum;
            }
            pv[r] = p;
        }

        // rank-32 V update; V row reused across the 4 query rows
        #pragma unroll 8
        for (int j = 0; j < TK; j++) {
            float p0 = __shfl_sync(0xffffffffu, pv[0], j);
            float p1 = __shfl_sync(0xffffffffu, pv[1], j);
            float p2 = __shfl_sync(0xffffffffu, pv[2], j);
            float p3 = __shfl_sync(0xffffffffu, pv[3], j);
            const float* vr = &Vs[j*DV + lane];
            #pragma unroll
            for (int u = 0; u < UV; u++) {
                float v = vr[32*u];
                acc[0][u] = fmaf(p0, v, acc[0][u]);
                acc[1][u] = fmaf(p1, v, acc[1][u]);
                acc[2][u] = fmaf(p2, v, acc[2][u]);
                acc[3][u] = fmaf(p3, v, acc[3][u]);
            }
        }
    }

    #pragma unroll
    for (int r = 0; r < RW; r++) {
        float inv = 1.f / l_[r];
        int row = row0 + w*RW + r;
        float* orow = Om + (size_t)(b*S + row)*D + h*DV + lane;
        #pragma unroll
        for (int u = 0; u < UV; u++)
            orow[32*u] = acc[r][u] * inv;
    }
}

// ------------------------- SIMT GEMM: C = relu([A1|A2] @ W + bias) ---------
// 128x128x16 tile, 256 threads, 8x8 micro-tile. W: [(K1+K2), N] row-major.
__global__ void gemm_bias_relu_kernel(const float* __restrict__ A1, int K1,
                                      const float* __restrict__ A2, int K2,
                                      const float* __restrict__ W,
                                      const float* __restrict__ bias,
                                      float* __restrict__ C, int M, int N)
{
    constexpr int BM = 128, BN = 128, BK = 16;
    __shared__ float Ast[BK][BM+4];   // transposed A tile
    __shared__ float Bs [BK][BN+4];
    int tid = threadIdx.x;
    int bm = blockIdx.y * BM;
    int bn = blockIdx.x * BN;
    int tx = tid & 15, ty = tid >> 4;

    float acc[8][8];
    #pragma unroll
    for (int i = 0; i < 8; i++)
        #pragma unroll
        for (int j = 0; j < 8; j++) acc[i][j] = 0.f;

    int Ktot = K1 + K2;
    int ar  = tid >> 2;          // 0..63
    int ac4 = (tid & 3) * 4;
    int br  = tid >> 5;          // 0..7
    int bc4 = (tid & 31) * 4;

    for (int k0 = 0; k0 < Ktot; k0 += BK) {
        const float* A; int Ka, kk0;
        if (k0 < K1) { A = A1; Ka = K1; kk0 = k0; }
        else         { A = A2; Ka = K2; kk0 = k0 - K1; }
        #pragma unroll
        for (int rr = 0; rr < 2; rr++) {
            int row = ar + rr*64;
            float4 v = *(const float4*)&A[(size_t)(bm+row)*Ka + kk0 + ac4];
            Ast[ac4+0][row] = v.x;
            Ast[ac4+1][row] = v.y;
            Ast[ac4+2][row] = v.z;
            Ast[ac4+3][row] = v.w;
        }
        #pragma unroll
        for (int rr = 0; rr < 2; rr++) {
            float4 v = *(const float4*)&W[(size_t)(k0 + br + rr*8)*N + bn + bc4];
            *(float4*)&Bs[br + rr*8][bc4] = v;
        }
        __syncthreads();
        #pragma unroll
        for (int kk = 0; kk < BK; kk++) {
            float a[8], bv[8];
            *(float4*)&a[0]  = *(const float4*)&Ast[kk][ty*8];
            *(float4*)&a[4]  = *(const float4*)&Ast[kk][ty*8+4];
            *(float4*)&bv[0] = *(const float4*)&Bs[kk][tx*8];
            *(float4*)&bv[4] = *(const float4*)&Bs[kk][tx*8+4];
            #pragma unroll
            for (int i = 0; i < 8; i++)
                #pragma unroll
                for (int j = 0; j < 8; j++)
                    acc[i][j] = fmaf(a[i], bv[j], acc[i][j]);
        }
        __syncthreads();
    }

    #pragma unroll
    for (int i = 0; i < 8; i++) {
        int row = bm + ty*8 + i;
        #pragma unroll
        for (int j0 = 0; j0 < 8; j0 += 4) {
            int col = bn + tx*8 + j0;
            float4 o;
            o.x = fmaxf(acc[i][j0+0] + bias[col+0], 0.f);
            o.y = fmaxf(acc[i][j0+1] + bias[col+1], 0.f);
            o.z = fmaxf(acc[i][j0+2] + bias[col+2], 0.f);
            o.w = fmaxf(acc[i][j0+3] + bias[col+3], 0.f);
            *(float4*)&C[(size_t)row*N + col] = o;
        }
    }
}

// ------------------------- launcher ----------------------------------------
extern "C" void kernel_launch(void* const* d_in, const int* in_sizes, int n_in,
                              void* d_out, int out_size)
{
    const float* x    = (const float*)d_in[0];
    const int*   mask = (const int*)  d_in[1];
    const float* pos  = (const float*)d_in[2];
    const float* Wq   = (const float*)d_in[3];
    const float* bq   = (const float*)d_in[4];
    const float* Wk   = (const float*)d_in[5];
    const float* bk   = (const float*)d_in[6];
    const float* Wpam = (const float*)d_in[7];
    const float* bpam = (const float*)d_in[8];
    const float* Wm   = (const float*)d_in[9];
    const float* bm   = (const float*)d_in[10];
    float* out = (float*)d_out;

    float *gq, *gk, *gatt, *gpos, *gpam;
    cudaGetSymbolAddress((void**)&gq,   g_q);
    cudaGetSymbolAddress((void**)&gk,   g_k);
    cudaGetSymbolAddress((void**)&gatt, g_att);
    cudaGetSymbolAddress((void**)&gpos, g_pos);
    cudaGetSymbolAddress((void**)&gpam, g_pam);

    const int smem_sam = (32*(8+4)*2   + 32*192) * 4 + 32*4;   // ~27.8 KB
    const int smem_pam = (32*(192+4)*2 + 32*192) * 4 + 32*4;   // ~74.9 KB
    cudaFuncSetAttribute(attn_kernel<192>,
                         cudaFuncAttributeMaxDynamicSharedMemorySize, smem_pam);

    const float scale_sam = (float)pow(8.0,   -0.25);
    const float scale_pam = (float)pow(192.0, -0.25);

    // 1) q/k projections (relu)
    qk_proj_kernel<<<B*S/4, 256>>>(x, Wq, bq, Wk, bk, gq, gk);

    dim3 agrid(S/32, H, B);
    // 2) SAM attention: softmax over query axis == std attention with Q<->K swap
    attn_kernel<8><<<agrid, 256, smem_sam>>>(gk, gq, AD, x, mask, gatt, scale_sam);
    // 3) PAM attention: Q = K = position
    attn_kernel<192><<<agrid, 256, smem_pam>>>(pos, pos, D, x, mask, gpos, scale_pam);

    dim3 ggrid(D/128, (B*S)/128);
    // 4) pam = relu(pos_out @ Wpam + bpam)
    gemm_bias_relu_kernel<<<ggrid, 256>>>(gpos, D, nullptr, 0, Wpam, bpam, gpam, B*S, D);
    // 5) out = relu([att | pam] @ Wm + bm)  (two-segment K loop, no concat copy)
    gemm_bias_relu_kernel<<<ggrid, 256>>>(gatt, D, gpam, D, Wm, bm, out, B*S, D);
}

// round 11
// speedup vs baseline: 1.0019x; 1.0019x over previous
#include <cuda_runtime.h>
#include <cmath>

#define B 8
#define S 1024
#define D 768
#define H 4
#define DV 192
#define AD 32

// ------------------------- scratch (device globals, no allocs) -------------
__device__ float g_q[B*S*AD];
__device__ float g_k[B*S*AD];
__device__ float g_att[B*S*D];
__device__ float g_pos[B*S*D];
__device__ float g_pam[B*S*D];

// ------------------------- q/k projection: relu(x@W + b), D->32 ------------
__global__ void qk_proj_kernel(const float* __restrict__ x,
                               const float* __restrict__ Wq, const float* __restrict__ bq,
                               const float* __restrict__ Wk, const float* __restrict__ bk,
                               float* __restrict__ qo, float* __restrict__ ko)
{
    __shared__ float xs[4*D];
    int row0 = blockIdx.x * 4;
    int tid = threadIdx.x;
    const float4* xg = (const float4*)(x + (size_t)row0 * D);
    for (int i = tid; i < 4*D/4; i += 256)
        ((float4*)xs)[i] = xg[i];
    __syncthreads();
    int g = tid >> 6;          // 4 rows per block
    int c = tid & 63;          // 0..31 -> q cols, 32..63 -> k cols
    const float* xr = xs + g * D;
    const float* W = (c < AD) ? Wq : Wk;
    int col = c & (AD-1);
    float s = 0.f;
    #pragma unroll 8
    for (int d = 0; d < D; d++)
        s = fmaf(xr[d], W[d*AD + col], s);
    s += (c < AD) ? bq[col] : bk[col];
    s = fmaxf(s, 0.f);
    int row = row0 + g;
    float* o = (c < AD) ? qo : ko;
    o[(size_t)row*AD + col] = s;
}

// ------------------------- fused flash attention ---------------------------
// out[b, i, h*DV + d] = sum_j softmax_j( Q[i]·K[j] * scale, masked ) * V[j, d]
// mask(i,j) invalid -> score = -1e7f (finite, matches reference semantics:
// an all-masked row degenerates to a uniform average, NOT zeros).
template<int DQK>
__global__ void attn_kernel(const float* __restrict__ Qm,
                            const float* __restrict__ Km,
                            int qk_stride,
                            const float* __restrict__ Vm,   // x [B,S,D]
                            const int* __restrict__ mask,   // [B,S]
                            float* __restrict__ Om,         // [B,S,D]
                            float scale)
{
    constexpr int TK = 32;           // keys per tile
    constexpr int RW = 4;            // rows per warp
    constexpr int NW = 8;            // warps per block
    constexpr int RB = RW*NW;        // 32 rows per block
    constexpr int KSs = DQK + 4;     // padded row stride (== 4 mod 32: float4-phase friendly)
    constexpr int UV = DV/32;        // 6 v-columns per lane

    extern __shared__ float smem[];
    float* Qs = smem;                    // RB*KSs
    float* Ks = Qs + RB*KSs;             // TK*KSs
    float* Vs = Ks + TK*KSs;             // TK*DV
    int*   kms = (int*)(Vs + TK*DV);     // TK

    int b = blockIdx.z, h = blockIdx.y;
    int row0 = blockIdx.x * RB;
    int tid = threadIdx.x;
    int lane = tid & 31;
    int w = tid >> 5;

    const float* Qbase = Qm + (size_t)b*S*qk_stride + h*DQK;
    const float* Kbase = Km + (size_t)b*S*qk_stride + h*DQK;
    const float* Vbase = Vm + (size_t)b*S*D + h*DV;
    const int* mb = mask + b*S;

    // load the 32 query rows once
    for (int i = tid; i < RB*DQK; i += NW*32) {
        int r = i / DQK, d = i % DQK;
        Qs[r*KSs + d] = Qbase[(size_t)(row0 + r)*qk_stride + d];
    }

    int rmask[RW];
    #pragma unroll
    for (int r = 0; r < RW; r++) rmask[r] = mb[row0 + w*RW + r];

    float m_[RW], l_[RW], acc[RW][UV];
    #pragma unroll
    for (int r = 0; r < RW; r++) {
        m_[r] = -INFINITY; l_[r] = 0.f;
        #pragma unroll
        for (int u = 0; u < UV; u++) acc[r][u] = 0.f;
    }

    for (int t = 0; t < S/TK; t++) {
        int k0 = t * TK;
        __syncthreads();
        // K tile
        for (int i = tid; i < TK*(DQK/4); i += NW*32) {
            int j = i / (DQK/4), d4 = i % (DQK/4);
            float4 v = *(const float4*)&Kbase[(size_t)(k0+j)*qk_stride + d4*4];
            float* kd = &Ks[j*KSs + d4*4];
            kd[0]=v.x; kd[1]=v.y; kd[2]=v.z; kd[3]=v.w;
        }
        // V tile
        for (int i = tid; i < TK*(DV/4); i += NW*32) {
            int j = i / (DV/4), d4 = i % (DV/4);
            *(float4*)&Vs[j*DV + d4*4] =
                *(const float4*)&Vbase[(size_t)(k0+j)*D + d4*4];
        }
        if (tid < TK) kms[tid] = mb[k0 + tid];
        __syncthreads();

        int km = kms[lane];
        const float* krow = &Ks[lane*KSs];
        float s4[RW];
        #pragma unroll
        for (int r = 0; r < RW; r++) s4[r] = 0.f;
        #pragma unroll 8
        for (int d4 = 0; d4 < DQK/4; d4++) {
            float4 kb = *(const float4*)&krow[d4*4];
            #pragma unroll
            for (int r = 0; r < RW; r++) {
                float4 qa = *(const float4*)&Qs[(w*RW+r)*KSs + d4*4];
                s4[r] = fmaf(qa.x, kb.x, s4[r]);
                s4[r] = fmaf(qa.y, kb.y, s4[r]);
                s4[r] = fmaf(qa.z, kb.z, s4[r]);
                s4[r] = fmaf(qa.w, kb.w, s4[r]);
            }
        }

        float pv[RW];
        #pragma unroll
        for (int r = 0; r < RW; r++) {
            float s = s4[r] * scale;
            s = (rmask[r] && km) ? s : -1e7f;
            float tmax = s;
            #pragma unroll
            for (int o = 16; o; o >>= 1)
                tmax = fmaxf(tmax, __shfl_xor_sync(0xffffffffu, tmax, o));
            float mnew = fmaxf(m_[r], tmax);
            float p = __expf(s - mnew);
            float psum = p;
            #pragma unroll
            for (int o = 16; o; o >>= 1)
                psum += __shfl_xor_sync(0xffffffffu, psum, o);
            if (mnew > m_[r]) {                        // warp-uniform branch
                float alpha = __expf(m_[r] - mnew);    // exp(-inf)=0 handles init
                l_[r] = fmaf(l_[r], alpha, psum);
                #pragma unroll
                for (int u = 0; u < UV; u++) acc[r][u] *= alpha;
                m_[r] = mnew;
            } else {
                l_[r] += psum;
            }
            pv[r] = p;
        }

        // rank-32 V update; V row reused across the 4 query rows
        #pragma unroll 8
        for (int j = 0; j < TK; j++) {
            float p0 = __shfl_sync(0xffffffffu, pv[0], j);
            float p1 = __shfl_sync(0xffffffffu, pv[1], j);
            float p2 = __shfl_sync(0xffffffffu, pv[2], j);
            float p3 = __shfl_sync(0xffffffffu, pv[3], j);
            const float* vr = &Vs[j*DV + lane];
            #pragma unroll
            for (int u = 0; u < UV; u++) {
                float v = vr[32*u];
                acc[0][u] = fmaf(p0, v, acc[0][u]);
                acc[1][u] = fmaf(p1, v, acc[1][u]);
                acc[2][u] = fmaf(p2, v, acc[2][u]);
                acc[3][u] = fmaf(p3, v, acc[3][u]);
            }
        }
    }

    #pragma unroll
    for (int r = 0; r < RW; r++) {
        float inv = 1.f / l_[r];
        int row = row0 + w*RW + r;
        float* orow = Om + (size_t)(b*S + row)*D + h*DV + lane;
        #pragma unroll
        for (int u = 0; u < UV; u++)
            orow[32*u] = acc[r][u] * inv;
    }
}

// ------------------------- SIMT GEMM: C = relu([A1|A2] @ W + bias) ---------
// 128x128x16 tile, 256 threads, 8x8 micro-tile. W: [(K1+K2), N] row-major.
__global__ void gemm_bias_relu_kernel(const float* __restrict__ A1, int K1,
                                      const float* __restrict__ A2, int K2,
                                      const float* __restrict__ W,
                                      const float* __restrict__ bias,
                                      float* __restrict__ C, int M, int N)
{
    constexpr int BM = 128, BN = 128, BK = 16;
    __shared__ float Ast[BK][BM+4];   // transposed A tile
    __shared__ float Bs [BK][BN+4];
    int tid = threadIdx.x;
    int bm = blockIdx.y * BM;
    int bn = blockIdx.x * BN;
    int tx = tid & 15, ty = tid >> 4;

    float acc[8][8];
    #pragma unroll
    for (int i = 0; i < 8; i++)
        #pragma unroll
        for (int j = 0; j < 8; j++) acc[i][j] = 0.f;

    int Ktot = K1 + K2;
    int ar  = tid >> 2;          // 0..63
    int ac4 = (tid & 3) * 4;
    int br  = tid >> 5;          // 0..7
    int bc4 = (tid & 31) * 4;

    for (int k0 = 0; k0 < Ktot; k0 += BK) {
        const float* A; int Ka, kk0;
        if (k0 < K1) { A = A1; Ka = K1; kk0 = k0; }
        else         { A = A2; Ka = K2; kk0 = k0 - K1; }
        #pragma unroll
        for (int rr = 0; rr < 2; rr++) {
            int row = ar + rr*64;
            float4 v = *(const float4*)&A[(size_t)(bm+row)*Ka + kk0 + ac4];
            Ast[ac4+0][row] = v.x;
            Ast[ac4+1][row] = v.y;
            Ast[ac4+2][row] = v.z;
            Ast[ac4+3][row] = v.w;
        }
        #pragma unroll
        for (int rr = 0; rr < 2; rr++) {
            float4 v = *(const float4*)&W[(size_t)(k0 + br + rr*8)*N + bn + bc4];
            *(float4*)&Bs[br + rr*8][bc4] = v;
        }
        __syncthreads();
        #pragma unroll
        for (int kk = 0; kk < BK; kk++) {
            float a[8], bv[8];
            *(float4*)&a[0]  = *(const float4*)&Ast[kk][ty*8];
            *(float4*)&a[4]  = *(const float4*)&Ast[kk][ty*8+4];
            *(float4*)&bv[0] = *(const float4*)&Bs[kk][tx*8];
            *(float4*)&bv[4] = *(const float4*)&Bs[kk][tx*8+4];
            #pragma unroll
            for (int i = 0; i < 8; i++)
                #pragma unroll
                for (int j = 0; j < 8; j++)
                    acc[i][j] = fmaf(a[i], bv[j], acc[i][j]);
        }
        __syncthreads();
    }

    #pragma unroll
    for (int i = 0; i < 8; i++) {
        int row = bm + ty*8 + i;
        #pragma unroll
        for (int j0 = 0; j0 < 8; j0 += 4) {
            int col = bn + tx*8 + j0;
            float4 o;
            o.x = fmaxf(acc[i][j0+0] + bias[col+0], 0.f);
            o.y = fmaxf(acc[i][j0+1] + bias[col+1], 0.f);
            o.z = fmaxf(acc[i][j0+2] + bias[col+2], 0.f);
            o.w = fmaxf(acc[i][j0+3] + bias[col+3], 0.f);
            *(float4*)&C[(size_t)row*N + col] = o;
        }
    }
}

// ------------------------- launcher ----------------------------------------
extern "C" void kernel_launch(void* const* d_in, const int* in_sizes, int n_in,
                              void* d_out, int out_size)
{
    const float* x    = (const float*)d_in[0];
    const int*   mask = (const int*)  d_in[1];
    const float* pos  = (const float*)d_in[2];
    const float* Wq   = (const float*)d_in[3];
    const float* bq   = (const float*)d_in[4];
    const float* Wk   = (const float*)d_in[5];
    const float* bk   = (const float*)d_in[6];
    const float* Wpam = (const float*)d_in[7];
    const float* bpam = (const float*)d_in[8];
    const float* Wm   = (const float*)d_in[9];
    const float* bm   = (const float*)d_in[10];
    float* out = (float*)d_out;

    float *gq, *gk, *gatt, *gpos, *gpam;
    cudaGetSymbolAddress((void**)&gq,   g_q);
    cudaGetSymbolAddress((void**)&gk,   g_k);
    cudaGetSymbolAddress((void**)&gatt, g_att);
    cudaGetSymbolAddress((void**)&gpos, g_pos);
    cudaGetSymbolAddress((void**)&gpam, g_pam);

    const int smem_sam = (32*(8+4)*2   + 32*192) * 4 + 32*4;   // ~27.8 KB
    const int smem_pam = (32*(192+4)*2 + 32*192) * 4 + 32*4;   // ~74.9 KB
    cudaFuncSetAttribute(attn_kernel<192>,
                         cudaFuncAttributeMaxDynamicSharedMemorySize, smem_pam);

    const float scale_sam = (float)pow(8.0,   -0.25);
    const float scale_pam = (float)pow(192.0, -0.25);

    // 1) q/k projections (relu)
    qk_proj_kernel<<<B*S/4, 256>>>(x, Wq, bq, Wk, bk, gq, gk);

    dim3 agrid(S/32, H, B);
    // 2) SAM attention: softmax over query axis == std attention with Q<->K swap
    attn_kernel<8><<<agrid, 256, smem_sam>>>(gk, gq, AD, x, mask, gatt, scale_sam);
    // 3) PAM attention: Q = K = position
    attn_kernel<192><<<agrid, 256, smem_pam>>>(pos, pos, D, x, mask, gpos, scale_pam);

    dim3 ggrid(D/128, (B*S)/128);
    // 4) pam = relu(pos_out @ Wpam + bpam)
    gemm_bias_relu_kernel<<<ggrid, 256>>>(gpos, D, nullptr, 0, Wpam, bpam, gpam, B*S, D);
    // 5) out = relu([att | pam] @ Wm + bm)  (two-segment K loop, no concat copy)
    gemm_bias_relu_kernel<<<ggrid, 256>>>(gatt, D, gpam, D, Wm, bm, out, B*S, D);
}